// round 8
// baseline (speedup 1.0000x reference)
#include <cuda_runtime.h>

#define PP 32768
#define LL 16
#define KK 8
#define HH 128

// Full h buffer for all L*P nodes (pred holds GLOBAL indices). 256 MiB static.
__device__ float g_h[(long long)LL * PP * HH];

__device__ __forceinline__ float lrelu(float x) { return x > 0.0f ? x : 0.1f * x; }
__device__ __forceinline__ float relu_(float x) { return x > 0.0f ? x : 0.0f; }

// ---------------------------------------------------------------------------
// h[0:P] = mlp2(delay, pi)   (unchanged)
// ---------------------------------------------------------------------------
__global__ void __launch_bounds__(256, 1)
k_init(const float* __restrict__ delay,
       const float* __restrict__ w1, const float* __restrict__ b1,
       const float* __restrict__ w2, const float* __restrict__ b2)
{
    extern __shared__ float smem[];
    float* s_t1 = smem;            // 64*64
    float* s_w2 = s_t1 + 64 * 64;  // 64*128
    float* s_b2 = s_w2 + 64 * 128; // 128

    const int tid  = threadIdx.x;
    const int row0 = blockIdx.x * 64;

    for (int i = tid; i < (64 * 128) / 4; i += 256)
        ((float4*)s_w2)[i] = ((const float4*)w2)[i];
    for (int i = tid; i < 128; i += 256) s_b2[i] = b2[i];
    for (int i = tid; i < 64 * 64; i += 256) {
        int r = i >> 6, c = i & 63;
        s_t1[i] = lrelu(delay[row0 + r] * w1[c] + b1[c]);
    }
    __syncthreads();

    const int w = tid >> 5, l = tid & 31;
    const int r0 = w * 8, c0 = l * 4;
    float acc[8][4];
#pragma unroll
    for (int r = 0; r < 8; r++)
#pragma unroll
        for (int c = 0; c < 4; c++) acc[r][c] = 0.0f;

#pragma unroll 4
    for (int k = 0; k < 64; k += 2) {
        float4 w0  = *(const float4*)(s_w2 + k * 128 + c0);
        float4 w1v = *(const float4*)(s_w2 + (k + 1) * 128 + c0);
#pragma unroll
        for (int r = 0; r < 8; r++) {
            float2 a = *(const float2*)(s_t1 + (r0 + r) * 64 + k);
            acc[r][0] = fmaf(a.x, w0.x, acc[r][0]); acc[r][0] = fmaf(a.y, w1v.x, acc[r][0]);
            acc[r][1] = fmaf(a.x, w0.y, acc[r][1]); acc[r][1] = fmaf(a.y, w1v.y, acc[r][1]);
            acc[r][2] = fmaf(a.x, w0.z, acc[r][2]); acc[r][2] = fmaf(a.y, w1v.z, acc[r][2]);
            acc[r][3] = fmaf(a.x, w0.w, acc[r][3]); acc[r][3] = fmaf(a.y, w1v.w, acc[r][3]);
        }
    }
#pragma unroll
    for (int r = 0; r < 8; r++) {
        float4 o;
        o.x = acc[r][0] + s_b2[c0 + 0];
        o.y = acc[r][1] + s_b2[c0 + 1];
        o.z = acc[r][2] + s_b2[c0 + 2];
        o.w = acc[r][3] + s_b2[c0 + 3];
        *(float4*)(g_h + (long long)(row0 + r0 + r) * HH + c0) = o;
    }
}

// ---------------------------------------------------------------------------
// Layer i (i=1..15). 128 thr / 64 rows / block, 43KB smem, 4 blocks/SM.
// grid = 512 <= 148*4 -> single wave. 16 rows per warp: each weight LDG
// feeds 16 rows (halved weight wavefronts vs 8-row tile).
// Weights read directly from global (L1/L2-resident) — no staging.
// ---------------------------------------------------------------------------
template <bool DO_RELU>
__global__ void __launch_bounds__(128, 4)
k_layer(int lo,
        const int*   __restrict__ pred,   // this layer's slice: PP*KK
        const float* __restrict__ feat,
        const float* __restrict__ ne_w1, const float* __restrict__ ne_b1,
        const float* __restrict__ ne_w2, const float* __restrict__ ne_b2,
        const float* __restrict__ sf_w1, const float* __restrict__ sf_b1,
        const float* __restrict__ sf_w2, const float* __restrict__ sf_b2)
{
    extern __shared__ float smem[];
    float* s_nt  = smem;            // 64*128 = 8192 floats (neigh, then t)
    float* s_ft  = smem + 8192;     // 64*32 = 2048
    float* s_b1  = smem + 10240;    // 128
    float* s_b2  = smem + 10368;    // 128
    int*   s_pred = (int*)(smem + 10496);  // 512 ints
    // total 11008 floats = 44032 B

    const int tid  = threadIdx.x;
    const int row0 = blockIdx.x * 64;

    // ---- preload ft, pred, biases ----
    for (int i = tid; i < 512; i += 128) {
        int r = i >> 3, c4 = i & 7;
        ((float4*)(s_ft + r * 32))[c4] =
            *((const float4*)(feat + (long long)(lo + row0 + r) * 32) + c4);
    }
    for (int i = tid; i < 512; i += 128)
        s_pred[i] = pred[(long long)row0 * KK + i];
    if (tid < 128) {
        s_b1[tid] = (tid < 64) ? ne_b1[tid] : sf_b1[tid - 64];
        s_b2[tid] = ne_b2[tid] + sf_b2[tid];
    }
    __syncthreads();

    // ---- gather mean of 8 predecessor rows: 64 rows x 32 c4 = 2048 tasks ----
#pragma unroll
    for (int j = 0; j < 16; j++) {
        int task = tid + j * 128;
        int r = task >> 5, c4 = task & 31;
        const int* pr = s_pred + r * 8;
        float x = 0.f, y = 0.f, z = 0.f, ww = 0.f;
#pragma unroll
        for (int k = 0; k < 8; k++) {
            const float4 v = *((const float4*)(g_h + (long long)pr[k] * HH) + c4);
            x += v.x; y += v.y; z += v.z; ww += v.w;
        }
        *((float4*)(s_nt + r * 128) + c4) =
            make_float4(x * 0.125f, y * 0.125f, z * 0.125f, ww * 0.125f);
    }
    __syncthreads();   // only block sync after preload (gather is cross-warp)

    const int w = tid >> 5, l = tid & 31;     // 4 warps; warp owns 16 rows
    const int r0 = w * 16;
    // stage-1 mapping: half-warp = 8 rows, (l&15)*4 = 4 cols
    const int r1 = r0 + (l >> 4) * 8;
    const int cg = (l & 15) * 4;

    // ---- stage 1, ne path: k=128, weights streamed from global ----
    float accA[8][4];
#pragma unroll
    for (int i = 0; i < 8; i++)
#pragma unroll
        for (int c = 0; c < 4; c++) accA[i][c] = 0.f;

#pragma unroll 2
    for (int k = 0; k < 128; k += 4) {
        float4 wv0 = *(const float4*)(ne_w1 + (k + 0) * 64 + cg);
        float4 wv1 = *(const float4*)(ne_w1 + (k + 1) * 64 + cg);
        float4 wv2 = *(const float4*)(ne_w1 + (k + 2) * 64 + cg);
        float4 wv3 = *(const float4*)(ne_w1 + (k + 3) * 64 + cg);
#pragma unroll
        for (int i = 0; i < 8; i++) {
            float4 a = *(const float4*)(s_nt + (r1 + i) * 128 + k);
            accA[i][0] = fmaf(a.x, wv0.x, accA[i][0]); accA[i][0] = fmaf(a.y, wv1.x, accA[i][0]);
            accA[i][0] = fmaf(a.z, wv2.x, accA[i][0]); accA[i][0] = fmaf(a.w, wv3.x, accA[i][0]);
            accA[i][1] = fmaf(a.x, wv0.y, accA[i][1]); accA[i][1] = fmaf(a.y, wv1.y, accA[i][1]);
            accA[i][1] = fmaf(a.z, wv2.y, accA[i][1]); accA[i][1] = fmaf(a.w, wv3.y, accA[i][1]);
            accA[i][2] = fmaf(a.x, wv0.z, accA[i][2]); accA[i][2] = fmaf(a.y, wv1.z, accA[i][2]);
            accA[i][2] = fmaf(a.z, wv2.z, accA[i][2]); accA[i][2] = fmaf(a.w, wv3.z, accA[i][2]);
            accA[i][3] = fmaf(a.x, wv0.w, accA[i][3]); accA[i][3] = fmaf(a.y, wv1.w, accA[i][3]);
            accA[i][3] = fmaf(a.z, wv2.w, accA[i][3]); accA[i][3] = fmaf(a.w, wv3.w, accA[i][3]);
        }
    }
    __syncwarp();   // all lanes done reading neigh before t_ne overwrites

    // t_ne -> s_nt cols [cg, cg+4) of own 8 rows
#pragma unroll
    for (int i = 0; i < 8; i++) {
        float4 o;
        o.x = lrelu(accA[i][0] + s_b1[cg + 0]);
        o.y = lrelu(accA[i][1] + s_b1[cg + 1]);
        o.z = lrelu(accA[i][2] + s_b1[cg + 2]);
        o.w = lrelu(accA[i][3] + s_b1[cg + 3]);
        *(float4*)(s_nt + (r1 + i) * 128 + cg) = o;
    }

    // ---- stage 1, sf path: k=32 over s_ft (weights from global) ----
    float accB[8][4];
#pragma unroll
    for (int i = 0; i < 8; i++)
#pragma unroll
        for (int c = 0; c < 4; c++) accB[i][c] = 0.f;

#pragma unroll 2
    for (int k = 0; k < 32; k += 4) {
        float4 wv0 = *(const float4*)(sf_w1 + (k + 0) * 64 + cg);
        float4 wv1 = *(const float4*)(sf_w1 + (k + 1) * 64 + cg);
        float4 wv2 = *(const float4*)(sf_w1 + (k + 2) * 64 + cg);
        float4 wv3 = *(const float4*)(sf_w1 + (k + 3) * 64 + cg);
#pragma unroll
        for (int i = 0; i < 8; i++) {
            float4 a = *(const float4*)(s_ft + (r1 + i) * 32 + k);
            accB[i][0] = fmaf(a.x, wv0.x, accB[i][0]); accB[i][0] = fmaf(a.y, wv1.x, accB[i][0]);
            accB[i][0] = fmaf(a.z, wv2.x, accB[i][0]); accB[i][0] = fmaf(a.w, wv3.x, accB[i][0]);
            accB[i][1] = fmaf(a.x, wv0.y, accB[i][1]); accB[i][1] = fmaf(a.y, wv1.y, accB[i][1]);
            accB[i][1] = fmaf(a.z, wv2.y, accB[i][1]); accB[i][1] = fmaf(a.w, wv3.y, accB[i][1]);
            accB[i][2] = fmaf(a.x, wv0.z, accB[i][2]); accB[i][2] = fmaf(a.y, wv1.z, accB[i][2]);
            accB[i][2] = fmaf(a.z, wv2.z, accB[i][2]); accB[i][2] = fmaf(a.w, wv3.z, accB[i][2]);
            accB[i][3] = fmaf(a.x, wv0.w, accB[i][3]); accB[i][3] = fmaf(a.y, wv1.w, accB[i][3]);
            accB[i][3] = fmaf(a.z, wv2.w, accB[i][3]); accB[i][3] = fmaf(a.w, wv3.w, accB[i][3]);
        }
    }
    // t_sf -> s_nt cols [64+cg, 64+cg+4) of own 8 rows
#pragma unroll
    for (int i = 0; i < 8; i++) {
        float4 o;
        o.x = lrelu(accB[i][0] + s_b1[64 + cg + 0]);
        o.y = lrelu(accB[i][1] + s_b1[64 + cg + 1]);
        o.z = lrelu(accB[i][2] + s_b1[64 + cg + 2]);
        o.w = lrelu(accB[i][3] + s_b1[64 + cg + 3]);
        *(float4*)(s_nt + (r1 + i) * 128 + 64 + cg) = o;
    }
    __syncwarp();   // t complete for this warp's 16 rows (warp-local)

    // ---- stage 2: k=128 (ne_w2 for t cols 0..63, sf_w2 for 64..127) ----
    const int c0 = l * 4;
    float acc[16][4];
#pragma unroll
    for (int r = 0; r < 16; r++) { acc[r][0] = acc[r][1] = acc[r][2] = acc[r][3] = 0.f; }

#pragma unroll 1
    for (int k = 0; k < 64; k += 4) {
        float4 wv0 = *(const float4*)(ne_w2 + (k + 0) * 128 + c0);
        float4 wv1 = *(const float4*)(ne_w2 + (k + 1) * 128 + c0);
        float4 wv2 = *(const float4*)(ne_w2 + (k + 2) * 128 + c0);
        float4 wv3 = *(const float4*)(ne_w2 + (k + 3) * 128 + c0);
#pragma unroll
        for (int r = 0; r < 16; r++) {
            float4 a = *(const float4*)(s_nt + (r0 + r) * 128 + k);
            acc[r][0] = fmaf(a.x, wv0.x, acc[r][0]); acc[r][0] = fmaf(a.y, wv1.x, acc[r][0]);
            acc[r][0] = fmaf(a.z, wv2.x, acc[r][0]); acc[r][0] = fmaf(a.w, wv3.x, acc[r][0]);
            acc[r][1] = fmaf(a.x, wv0.y, acc[r][1]); acc[r][1] = fmaf(a.y, wv1.y, acc[r][1]);
            acc[r][1] = fmaf(a.z, wv2.y, acc[r][1]); acc[r][1] = fmaf(a.w, wv3.y, acc[r][1]);
            acc[r][2] = fmaf(a.x, wv0.z, acc[r][2]); acc[r][2] = fmaf(a.y, wv1.z, acc[r][2]);
            acc[r][2] = fmaf(a.z, wv2.z, acc[r][2]); acc[r][2] = fmaf(a.w, wv3.z, acc[r][2]);
            acc[r][3] = fmaf(a.x, wv0.w, acc[r][3]); acc[r][3] = fmaf(a.y, wv1.w, acc[r][3]);
            acc[r][3] = fmaf(a.z, wv2.w, acc[r][3]); acc[r][3] = fmaf(a.w, wv3.w, acc[r][3]);
        }
    }
#pragma unroll 1
    for (int k = 0; k < 64; k += 4) {
        float4 wv0 = *(const float4*)(sf_w2 + (k + 0) * 128 + c0);
        float4 wv1 = *(const float4*)(sf_w2 + (k + 1) * 128 + c0);
        float4 wv2 = *(const float4*)(sf_w2 + (k + 2) * 128 + c0);
        float4 wv3 = *(const float4*)(sf_w2 + (k + 3) * 128 + c0);
#pragma unroll
        for (int r = 0; r < 16; r++) {
            float4 a = *(const float4*)(s_nt + (r0 + r) * 128 + 64 + k);
            acc[r][0] = fmaf(a.x, wv0.x, acc[r][0]); acc[r][0] = fmaf(a.y, wv1.x, acc[r][0]);
            acc[r][0] = fmaf(a.z, wv2.x, acc[r][0]); acc[r][0] = fmaf(a.w, wv3.x, acc[r][0]);
            acc[r][1] = fmaf(a.x, wv0.y, acc[r][1]); acc[r][1] = fmaf(a.y, wv1.y, acc[r][1]);
            acc[r][1] = fmaf(a.z, wv2.y, acc[r][1]); acc[r][1] = fmaf(a.w, wv3.y, acc[r][1]);
            acc[r][2] = fmaf(a.x, wv0.z, acc[r][2]); acc[r][2] = fmaf(a.y, wv1.z, acc[r][2]);
            acc[r][2] = fmaf(a.z, wv2.z, acc[r][2]); acc[r][2] = fmaf(a.w, wv3.z, acc[r][2]);
            acc[r][3] = fmaf(a.x, wv0.w, acc[r][3]); acc[r][3] = fmaf(a.y, wv1.w, acc[r][3]);
            acc[r][3] = fmaf(a.z, wv2.w, acc[r][3]); acc[r][3] = fmaf(a.w, wv3.w, acc[r][3]);
        }
    }

    // ---- epilogue ----
#pragma unroll
    for (int r = 0; r < 16; r++) {
        float4 o;
        o.x = acc[r][0] + s_b2[c0 + 0];
        o.y = acc[r][1] + s_b2[c0 + 1];
        o.z = acc[r][2] + s_b2[c0 + 2];
        o.w = acc[r][3] + s_b2[c0 + 3];
        if (DO_RELU) { o.x = relu_(o.x); o.y = relu_(o.y); o.z = relu_(o.z); o.w = relu_(o.w); }
        *(float4*)(g_h + (long long)(lo + row0 + r0 + r) * HH + c0) = o;
    }
}

// ---------------------------------------------------------------------------
// Final head (unchanged)
// ---------------------------------------------------------------------------
__global__ void __launch_bounds__(256, 1)
k_final(const float* __restrict__ PO,
        const float* __restrict__ gl_w1, const float* __restrict__ gl_b1,
        const float* __restrict__ gl_w2, const float* __restrict__ gl_b2,
        const float* __restrict__ out_w1, const float* __restrict__ out_b1,
        const float* __restrict__ out_w2, const float* __restrict__ out_b2,
        float* __restrict__ out)
{
    extern __shared__ float smem[];
    float* s_x   = smem;             // 64*256
    float* s_w   = s_x + 16384;      // 64*128
    float* s_t   = s_w + 8192;       // 64*132
    float* s_g1  = s_t + 8448;       // 64*64
    float* s_gb2 = s_g1 + 4096;      // 128
    float* s_ob1 = s_gb2 + 128;      // 128
    float* s_ow2 = s_ob1 + 128;      // 128

    const int tid  = threadIdx.x;
    const int row0 = blockIdx.x * 64;
    const long long gnn0 = (long long)(LL - 1) * PP * HH;

    for (int i = tid; i < 2048; i += 256)
        ((float4*)s_w)[i] = ((const float4*)gl_w2)[i];
    for (int i = tid; i < 128; i += 256) {
        s_gb2[i] = gl_b2[i];
        s_ob1[i] = out_b1[i];
        s_ow2[i] = out_w2[i];
    }
    for (int i = tid; i < 64 * 64; i += 256) {
        int r = i >> 6, c = i & 63;
        s_g1[i] = lrelu(PO[row0 + r] * gl_w1[c] + gl_b1[c]);
    }
    for (int i = tid; i < 2048; i += 256) {
        int r = i >> 5, c4 = i & 31;
        float4 v = *((const float4*)(g_h + gnn0 + (long long)(row0 + r) * HH) + c4);
        *((float4*)(s_x + r * 256) + c4) = v;
    }
    __syncthreads();

    const int w = tid >> 5, l = tid & 31;
    const int r0 = w * 8, c0 = l * 4;

    {
        float acc[8][4];
#pragma unroll
        for (int r = 0; r < 8; r++) { acc[r][0] = acc[r][1] = acc[r][2] = acc[r][3] = 0.f; }
#pragma unroll 4
        for (int k = 0; k < 64; k += 2) {
            float4 w0  = *(const float4*)(s_w + k * 128 + c0);
            float4 w1v = *(const float4*)(s_w + (k + 1) * 128 + c0);
#pragma unroll
            for (int r = 0; r < 8; r++) {
                float2 a = *(const float2*)(s_g1 + (r0 + r) * 64 + k);
                acc[r][0] = fmaf(a.x, w0.x, acc[r][0]); acc[r][0] = fmaf(a.y, w1v.x, acc[r][0]);
                acc[r][1] = fmaf(a.x, w0.y, acc[r][1]); acc[r][1] = fmaf(a.y, w1v.y, acc[r][1]);
                acc[r][2] = fmaf(a.x, w0.z, acc[r][2]); acc[r][2] = fmaf(a.y, w1v.z, acc[r][2]);
                acc[r][3] = fmaf(a.x, w0.w, acc[r][3]); acc[r][3] = fmaf(a.y, w1v.w, acc[r][3]);
            }
        }
#pragma unroll
        for (int r = 0; r < 8; r++) {
            float4 o;
            o.x = acc[r][0] + s_gb2[c0 + 0];
            o.y = acc[r][1] + s_gb2[c0 + 1];
            o.z = acc[r][2] + s_gb2[c0 + 2];
            o.w = acc[r][3] + s_gb2[c0 + 3];
            *(float4*)(s_x + (r0 + r) * 256 + 128 + c0) = o;
        }
    }

    float acc[8][4];
#pragma unroll
    for (int r = 0; r < 8; r++) { acc[r][0] = acc[r][1] = acc[r][2] = acc[r][3] = 0.f; }
    for (int kt = 0; kt < 4; kt++) {
        __syncthreads();
        const float4* src = (const float4*)(out_w1 + kt * 64 * 128);
        for (int i = tid; i < 2048; i += 256) ((float4*)s_w)[i] = src[i];
        __syncthreads();
#pragma unroll 4
        for (int k = 0; k < 64; k += 2) {
            float4 w0  = *(const float4*)(s_w + k * 128 + c0);
            float4 w1v = *(const float4*)(s_w + (k + 1) * 128 + c0);
#pragma unroll
            for (int r = 0; r < 8; r++) {
                float2 a = *(const float2*)(s_x + (r0 + r) * 256 + kt * 64 + k);
                acc[r][0] = fmaf(a.x, w0.x, acc[r][0]); acc[r][0] = fmaf(a.y, w1v.x, acc[r][0]);
                acc[r][1] = fmaf(a.x, w0.y, acc[r][1]); acc[r][1] = fmaf(a.y, w1v.y, acc[r][1]);
                acc[r][2] = fmaf(a.x, w0.z, acc[r][2]); acc[r][2] = fmaf(a.y, w1v.z, acc[r][2]);
                acc[r][3] = fmaf(a.x, w0.w, acc[r][3]); acc[r][3] = fmaf(a.y, w1v.w, acc[r][3]);
            }
        }
    }
#pragma unroll
    for (int r = 0; r < 8; r++) {
        float* t = s_t + (r0 + r) * 132;
        t[c0 + 0] = lrelu(acc[r][0] + s_ob1[c0 + 0]);
        t[c0 + 1] = lrelu(acc[r][1] + s_ob1[c0 + 1]);
        t[c0 + 2] = lrelu(acc[r][2] + s_ob1[c0 + 2]);
        t[c0 + 3] = lrelu(acc[r][3] + s_ob1[c0 + 3]);
    }
    __syncthreads();

    if (tid < 64) {
        float s = out_b2[0];
        const float* t = s_t + tid * 132;
#pragma unroll 8
        for (int k = 0; k < 128; k++) s = fmaf(t[k], s_ow2[k], s);
        out[row0 + tid] = s;
    }
}

// ---------------------------------------------------------------------------
extern "C" void kernel_launch(void* const* d_in, const int* in_sizes, int n_in,
                              void* d_out, int out_size)
{
    // Disambiguate input ordering via in_sizes[3] (pred=3932160 vs pi_w1=64).
    int idx_pred, idx_ispo, wbase;
    if (in_sizes[3] == (LL - 1) * PP * KK) { idx_pred = 3; idx_ispo = 4; wbase = 5; }
    else                                   { idx_pred = 23; idx_ispo = 24; wbase = 3; }
    (void)idx_ispo;

    const float* delay  = (const float*)d_in[0];
    const float* feat   = (const float*)d_in[1];
    const float* PO     = (const float*)d_in[2];
    const int*   pred   = (const int*)d_in[idx_pred];
    const float* pi_w1  = (const float*)d_in[wbase + 0];
    const float* pi_b1  = (const float*)d_in[wbase + 1];
    const float* pi_w2  = (const float*)d_in[wbase + 2];
    const float* pi_b2  = (const float*)d_in[wbase + 3];
    const float* ne_w1  = (const float*)d_in[wbase + 4];
    const float* ne_b1  = (const float*)d_in[wbase + 5];
    const float* ne_w2  = (const float*)d_in[wbase + 6];
    const float* ne_b2  = (const float*)d_in[wbase + 7];
    const float* sf_w1  = (const float*)d_in[wbase + 8];
    const float* sf_b1  = (const float*)d_in[wbase + 9];
    const float* sf_w2  = (const float*)d_in[wbase + 10];
    const float* sf_b2  = (const float*)d_in[wbase + 11];
    const float* gl_w1  = (const float*)d_in[wbase + 12];
    const float* gl_b1  = (const float*)d_in[wbase + 13];
    const float* gl_w2  = (const float*)d_in[wbase + 14];
    const float* gl_b2  = (const float*)d_in[wbase + 15];
    const float* out_w1 = (const float*)d_in[wbase + 16];
    const float* out_b1 = (const float*)d_in[wbase + 17];
    const float* out_w2 = (const float*)d_in[wbase + 18];
    const float* out_b2 = (const float*)d_in[wbase + 19];
    float* out = (float*)d_out;

    const size_t sh_init  = (size_t)(64 * 64 + 64 * 128 + 128) * 4;
    // layer: nt 8192 + ft 2048 + b1 128 + b2 128 + pred 512 = 11008 floats = 44032B
    const size_t sh_layer = (size_t)11008 * 4;
    const size_t sh_final = (size_t)(16384 + 8192 + 8448 + 4096 + 128 + 128 + 128) * 4;

    cudaFuncSetAttribute(k_init,  cudaFuncAttributeMaxDynamicSharedMemorySize, (int)sh_init);
    cudaFuncSetAttribute(k_layer<true>,  cudaFuncAttributeMaxDynamicSharedMemorySize, (int)sh_layer);
    cudaFuncSetAttribute(k_layer<false>, cudaFuncAttributeMaxDynamicSharedMemorySize, (int)sh_layer);
    cudaFuncSetAttribute(k_final, cudaFuncAttributeMaxDynamicSharedMemorySize, (int)sh_final);

    k_init<<<PP / 64, 256, sh_init>>>(delay, pi_w1, pi_b1, pi_w2, pi_b2);
    for (int i = 1; i < LL; i++) {
        const int* pl = pred + (long long)(i - 1) * PP * KK;
        if (i < LL - 1)
            k_layer<true><<<PP / 64, 128, sh_layer>>>(i * PP, pl, feat,
                ne_w1, ne_b1, ne_w2, ne_b2, sf_w1, sf_b1, sf_w2, sf_b2);
        else
            k_layer<false><<<PP / 64, 128, sh_layer>>>(i * PP, pl, feat,
                ne_w1, ne_b1, ne_w2, ne_b2, sf_w1, sf_b1, sf_w2, sf_b2);
    }
    k_final<<<PP / 64, 256, sh_final>>>(PO, gl_w1, gl_b1, gl_w2, gl_b2,
                                        out_w1, out_b1, out_w2, out_b2, out);
}